// round 9
// baseline (speedup 1.0000x reference)
#include <cuda_runtime.h>
#include <cuda_bf16.h>

#define L 128
#define GRID 152   // one persistent CTA per GB300 SM

__device__ __forceinline__ float sigmoidf(float x) {
    return 1.f / (1.f + __expf(-x));
}

// Persistent-CTA MFVI. Each CTA (512 threads) walks tiles bi = blockIdx.x +
// n*GRID. Register double-buffer: while the 3-iteration compute of tile t
// runs (barrier-synchronized, no DRAM traffic), the 8 LDG.128/thread for
// tile t+GRID are already in flight — DRAM streams continuously instead of
// the 70% duty cycle of the phase-structured one-tile-per-CTA version.
//
// Layout per tile: warp w (0..15) owns rows 8w..8w+7; lane l owns k in
// [4l,4l+4) for those rows (coalesced row loads: 4 lines per LDG.128).
// mask2o exclusions (k==i, k==row) are applied when copying the prefetch
// buffer into the live buffer (compile-time-indexed selects, no spills).
__global__ __launch_bounds__(512, 1)
void mfvi_kernel(const float* __restrict__ s_span,
                 const float* __restrict__ s_pair,
                 const unsigned int* __restrict__ mask,
                 float* __restrict__ out,
                 int BL)
{
    const int tid = threadIdx.x;
    const int w   = tid >> 5;              // warp id: rows 8w..8w+7
    const int l   = tid & 31;
    const int rg  = (w << 3) | (l & 7);    // row this lane finishes
    const int k0  = 4 * l;                 // this lane's k range [k0, k0+4)

    __shared__ float sig[L];

    int tile = blockIdx.x;
    if (tile >= BL) return;

    // Prologue: stream first tile into the prefetch buffer.
    float4 nb[8];
    {
        const size_t base = (size_t)tile * L;
        #pragma unroll
        for (int r = 0; r < 8; ++r) {
            const int row = (w << 3) + r;
            nb[r] = __ldcs(reinterpret_cast<const float4*>(
                               s_pair + (base + row) * L) + l);
        }
    }

    for (; tile < BL; tile += GRID) {
        const int i = tile & (L - 1);
        const size_t base = (size_t)tile * L;

        // Consume prefetch buffer -> live buffer, applying mask2o zeroing
        // (k == i or k == row). This is the only consumer of nb, so the
        // in-flight loads were covered by the previous tile's compute.
        float a[32];
        #pragma unroll
        for (int r = 0; r < 8; ++r) {
            const int row = (w << 3) + r;
            a[4*r+0] = (k0+0 == i || k0+0 == row) ? 0.f : nb[r].x;
            a[4*r+1] = (k0+1 == i || k0+1 == row) ? 0.f : nb[r].y;
            a[4*r+2] = (k0+2 == i || k0+2 == row) ? 0.f : nb[r].z;
            a[4*r+3] = (k0+3 == i || k0+3 == row) ? 0.f : nb[r].w;
        }

        // Prefetch next tile (pure streaming loads; complete under compute).
        const int nt = tile + GRID;
        if (nt < BL) {
            const size_t nbase = (size_t)nt * L;
            #pragma unroll
            for (int r = 0; r < 8; ++r) {
                const int row = (w << 3) + r;
                nb[r] = __ldcs(reinterpret_cast<const float4*>(
                                   s_pair + (nbase + row) * L) + l);
            }
        }

        const float sj    = s_span[base + rg];
        const float maskf = (mask[base + rg] != 0u) ? 1.f : 0.f;

        float q = sj;
        #pragma unroll
        for (int it = 0; it < 3; ++it) {
            if (l < 8) sig[rg] = sigmoidf(q);
            __syncthreads();

            // One conflict-free LDS.128: lane l reads sig[4l..4l+3]
            float4 sg = *reinterpret_cast<const float4*>(sig + k0);

            float p[8];
            #pragma unroll
            for (int r = 0; r < 8; ++r)
                p[r] = a[4*r+0]*sg.x + a[4*r+1]*sg.y
                     + a[4*r+2]*sg.z + a[4*r+3]*sg.w;

            // 3-stage multi-value butterfly over lane bits 0..2
            #pragma unroll
            for (int s = 0; s < 3; ++s) {
                const int m  = 1 << s;
                const int my = (l >> s) & 1;
                #pragma unroll
                for (int t = 0; t < (4 >> s); ++t) {
                    float keep = my ? p[2*t+1] : p[2*t];
                    float give = my ? p[2*t]   : p[2*t+1];
                    float recv = __shfl_xor_sync(0xffffffffu, give, m);
                    p[t] = keep + recv;
                }
            }
            // Combine the four 8-lane groups (distinct k-quarters)
            float tot = p[0];
            tot += __shfl_xor_sync(0xffffffffu, tot, 8);
            tot += __shfl_xor_sync(0xffffffffu, tot, 16);

            q = sj + maskf * tot;
            __syncthreads();   // sig reads done before next write
        }

        if (l < 8)
            out[base + rg] = sigmoidf(q);
        __syncthreads();       // sig stable before next tile's first write
    }
}

extern "C" void kernel_launch(void* const* d_in, const int* in_sizes, int n_in,
                              void* d_out, int out_size) {
    const float*        s_span = (const float*)d_in[0];
    const float*        s_pair = (const float*)d_in[1];
    const unsigned int* mask   = (const unsigned int*)d_in[2];
    float*              out    = (float*)d_out;

    const int BL = in_sizes[0] / L;   // B*L tiles
    mfvi_kernel<<<GRID, 512>>>(s_span, s_pair, mask, out, BL);
}